// round 5
// baseline (speedup 1.0000x reference)
#include <cuda_runtime.h>
#include <cuda_fp16.h>
#include <cstdint>

// ============================================================================
// Problem constants
// ============================================================================
#define D_IN   1024
#define D_OUT  2048
#define NROWS  8192               // 4 * 2048
#define KBAS   8192               // basis block: k = d*8 + j
#define KTOT   9216               // + silu block: k = 8192 + d
#define BM     128
#define BN     256
#define BK     64                 // 64 fp16 = 128B rows = SW128 atom
#define NSTEPS (KTOT / BK)        // 144  (multiple of NSTAGES -> cross-tile flow)
#define NSTAGES 4
#define NTILES ((NROWS / BM) * (D_OUT / BN))   // 512
#define GRIDP  148                              // persistent CTAs

// SMEM: 4 stages, each A(16KB) + B(32KB)
#define SM_A_STAGE 16384
#define SM_B_STAGE 32768
#define SM_B_BASE  (NSTAGES * SM_A_STAGE)                 // 65536
#define SMEM_TOTAL (SM_B_BASE + NSTAGES * SM_B_STAGE)     // 196608

// ============================================================================
// Device scratch (static __device__ arrays: sanctioned no-alloc workaround)
// ============================================================================
__device__ __half g_A[(size_t)NROWS * KTOT];   // 151 MB
__device__ __half g_W[(size_t)D_OUT * KTOT];   // 37.7 MB

// ============================================================================
// PTX helpers (base ISA only — harness builds for compute_103, no 'a')
// ============================================================================
__device__ __forceinline__ uint32_t smem_u32(const void* p) {
    uint32_t a;
    asm("{ .reg .u64 t; cvta.to.shared.u64 t, %1; cvt.u32.u64 %0, t; }" : "=r"(a) : "l"(p));
    return a;
}

__device__ __forceinline__ void cp16(uint32_t dst, const void* src) {
    asm volatile("cp.async.cg.shared.global [%0], [%1], 16;" :: "r"(dst), "l"(src));
}
#define CP_COMMIT() asm volatile("cp.async.commit_group;" ::: "memory")
#define CP_WAIT_2() asm volatile("cp.async.wait_group 2;" ::: "memory")

__device__ __forceinline__ void ldsm_x4(uint32_t* r, uint32_t addr) {
    asm volatile("ldmatrix.sync.aligned.m8n8.x4.shared.b16 {%0,%1,%2,%3}, [%4];"
                 : "=r"(r[0]), "=r"(r[1]), "=r"(r[2]), "=r"(r[3]) : "r"(addr));
}

__device__ __forceinline__ void mma_f16(float* c, const uint32_t* a,
                                        uint32_t b0, uint32_t b1) {
    asm volatile(
        "mma.sync.aligned.m16n8k16.row.col.f32.f16.f16.f32 "
        "{%0,%1,%2,%3}, {%4,%5,%6,%7}, {%8,%9}, {%0,%1,%2,%3};"
        : "+f"(c[0]), "+f"(c[1]), "+f"(c[2]), "+f"(c[3])
        : "r"(a[0]), "r"(a[1]), "r"(a[2]), "r"(a[3]), "r"(b0), "r"(b1));
}

// ============================================================================
// Prep kernel 1: basis block A[n][d*8+j] = B_j(x[n,d]); silu A[n][8192+d].
// Uniform knot grid -> all denominators are p*h: one rcp, zero divides.
// ============================================================================
__global__ void prep_A_kernel(const float* __restrict__ x, const float* __restrict__ grid) {
    int idx = blockIdx.x * blockDim.x + threadIdx.x;   // n*1024 + d
    int d = idx & (D_IN - 1);
    int n = idx >> 10;
    float xv = x[idx];
    float gv[12];
#pragma unroll
    for (int m = 0; m < 12; m++) gv[m] = __ldg(grid + d * 12 + m);

    const float invh  = __frcp_rn(gv[1] - gv[0]);
    const float invp[3] = {invh, 0.5f * invh, (1.0f / 3.0f) * invh};

    float B[11];
#pragma unroll
    for (int m = 0; m < 11; m++)
        B[m] = (xv >= gv[m] && xv < gv[m + 1]) ? 1.0f : 0.0f;
#pragma unroll
    for (int p = 1; p <= 3; p++) {
        const float ip = invp[p - 1];
#pragma unroll
        for (int m = 0; m < 11 - p; m++) {
            float left  = (xv - gv[m]) * ip;
            float right = (gv[m + p + 1] - xv) * ip;
            B[m] = left * B[m] + right * B[m + 1];
        }
    }
    __half2 h[4];
#pragma unroll
    for (int j = 0; j < 4; j++)
        h[j] = __floats2half2_rn(B[2 * j], B[2 * j + 1]);
    *reinterpret_cast<uint4*>(g_A + (size_t)n * KTOT + d * 8) =
        *reinterpret_cast<uint4*>(h);
    float s = xv * __frcp_rn(1.0f + __expf(-xv));
    g_A[(size_t)n * KTOT + KBAS + d] = __float2half_rn(s);
}

// ============================================================================
// Prep kernel 2: W[o][d*8+j] = coef[d][o][j]*ssp[d][o];  W[o][8192+d] = sb[d][o]
// ============================================================================
__global__ void prep_W_kernel(const float* __restrict__ coef,
                              const float* __restrict__ sb,
                              const float* __restrict__ ssp) {
    int idx = blockIdx.x * blockDim.x + threadIdx.x;  // d*2048 + o
    int o = idx & (D_OUT - 1);
    int d = idx >> 11;
    size_t doo = (size_t)d * D_OUT + o;
    float ss = ssp[doo];
    float4 c0 = *reinterpret_cast<const float4*>(coef + doo * 8);
    float4 c1 = *reinterpret_cast<const float4*>(coef + doo * 8 + 4);
    __half2 h[4];
    h[0] = __floats2half2_rn(c0.x * ss, c0.y * ss);
    h[1] = __floats2half2_rn(c0.z * ss, c0.w * ss);
    h[2] = __floats2half2_rn(c1.x * ss, c1.y * ss);
    h[3] = __floats2half2_rn(c1.z * ss, c1.w * ss);
    *reinterpret_cast<uint4*>(g_W + (size_t)o * KTOT + d * 8) =
        *reinterpret_cast<uint4*>(h);
    g_W[(size_t)o * KTOT + KBAS + d] = __float2half_rn(sb[doo]);
}

// ============================================================================
// Persistent GEMM: out[8192,2048] = A @ W^T  (fp16 m16n8k16, f32 acc)
// 148 CTAs x 512 thr (16 warps, warp tile 64x32). 4-stage cp.async pipeline
// flows ACROSS tile boundaries (NSTEPS % NSTAGES == 0) -> no re-prologue.
// ============================================================================
__global__ __launch_bounds__(512, 1)
void kan_gemm_kernel(float* __restrict__ out) {
    extern __shared__ __align__(128) char smem[];
    const uint32_t sbase = smem_u32(smem);
    const int tid  = threadIdx.x;
    const int lane = tid & 31;
    const int wid  = tid >> 5;          // 0..15
    const int wm   = wid & 1;           // 2 m-bands of 64
    const int wn   = wid >> 1;          // 8 n-bands of 32

    // ---- persistent tile list (n-fast order keeps W L2-resident) ----
    int myTiles[4], nt = 0;
    for (int t = blockIdx.x; t < NTILES; t += GRIDP) myTiles[nt++] = t;
    if (nt == 0) return;
    const int TOT = nt * NSTEPS;

    // ---- fill: A 128 rows x 8 units, B 256 rows x 8 units (16B units) ----
    const int fu = tid & 7;             // unit within 128B row
    const int fr = tid >> 3;            // base row (0..63)
    const int fsw = (fu ^ (fr & 7)) << 4;
    auto fill = [&](int s, int tile, int k) {
        const int m0 = (tile >> 3) * BM;
        const int n0 = (tile & 7) * BN;
        const __half* Asrc = g_A + (size_t)(m0 + fr) * KTOT + (size_t)k * BK + fu * 8;
        const __half* Bsrc = g_W + (size_t)(n0 + fr) * KTOT + (size_t)k * BK + fu * 8;
        uint32_t sA = sbase + s * SM_A_STAGE + fr * 128 + fsw;
        uint32_t sB = sbase + SM_B_BASE + s * SM_B_STAGE + fr * 128 + fsw;
#pragma unroll
        for (int i = 0; i < 2; i++)
            cp16(sA + i * 64 * 128, Asrc + (size_t)i * 64 * KTOT);
#pragma unroll
        for (int i = 0; i < 4; i++)
            cp16(sB + i * 64 * 128, Bsrc + (size_t)i * 64 * KTOT);
    };

    // Prologue: global steps 0..2
#pragma unroll
    for (int s = 0; s < NSTAGES - 1; s++) {
        fill(s, myTiles[0], s);
        CP_COMMIT();
    }

    float acc[4][4][4];
#pragma unroll
    for (int a = 0; a < 4; a++)
#pragma unroll
        for (int j = 0; j < 4; j++)
#pragma unroll
            for (int c = 0; c < 4; c++) acc[a][j][c] = 0.0f;

    // ldmatrix addressing (x4 = one 16x16 fp16 tile)
    const int s7  = lane & 7;
    const int hi  = lane >> 4;
    const int r16 = lane & 15;
    const uint32_t rowA_off = (uint32_t)(wm * 64 + r16) * 128;
    const uint32_t rowB_off = (uint32_t)(wn * 32 + r16) * 128;

    int k = 0, ti = 0;                  // current step-in-tile / tile index
    int kf = NSTAGES - 1, tif = 0;      // fill-ahead step / tile index

    for (int gk = 0; gk < TOT; gk++) {
        const int s = gk & (NSTAGES - 1);
        CP_WAIT_2();
        __syncthreads();

        if (gk + NSTAGES - 1 < TOT)
            fill((gk + NSTAGES - 1) & (NSTAGES - 1), myTiles[tif], kf);
        CP_COMMIT();
        if (++kf == NSTEPS) { kf = 0; tif++; }

        const uint32_t sA = sbase + s * SM_A_STAGE + rowA_off;
        const uint32_t sB = sbase + SM_B_BASE + s * SM_B_STAGE + rowB_off;
#pragma unroll
        for (int kc = 0; kc < 4; kc++) {
            const uint32_t u = ((uint32_t)((kc * 2 + hi) ^ s7)) << 4;
            uint32_t af[4][4], bf[2][4];
#pragma unroll
            for (int a = 0; a < 4; a++) ldsm_x4(af[a], sA + a * 2048 + u);
#pragma unroll
            for (int nb = 0; nb < 2; nb++) ldsm_x4(bf[nb], sB + nb * 2048 + u);
#pragma unroll
            for (int a = 0; a < 4; a++)
#pragma unroll
                for (int nb = 0; nb < 2; nb++) {
                    mma_f16(acc[a][nb * 2 + 0], af[a], bf[nb][0], bf[nb][2]);
                    mma_f16(acc[a][nb * 2 + 1], af[a], bf[nb][1], bf[nb][3]);
                }
        }

        if (++k == NSTEPS) {            // tile done: epilogue (regs only) + reset
            k = 0;
            const int tile = myTiles[ti++];
            const int m0 = (tile >> 3) * BM;
            const int n0 = (tile & 7) * BN;
            const int orow0 = m0 + wm * 64 + (lane >> 2);
            const int ocol0 = n0 + wn * 32 + (lane & 3) * 2;
#pragma unroll
            for (int a = 0; a < 4; a++) {
                float* p0 = out + (size_t)(orow0 + a * 16) * D_OUT + ocol0;
                float* p1 = p0 + 8 * D_OUT;
#pragma unroll
                for (int j = 0; j < 4; j++) {
                    *reinterpret_cast<float2*>(p0 + j * 8) =
                        make_float2(acc[a][j][0], acc[a][j][1]);
                    *reinterpret_cast<float2*>(p1 + j * 8) =
                        make_float2(acc[a][j][2], acc[a][j][3]);
                    acc[a][j][0] = acc[a][j][1] = acc[a][j][2] = acc[a][j][3] = 0.0f;
                }
            }
        }
    }
}

// ============================================================================
// Host launch (graph-capturable: kernel launches only)
// ============================================================================
extern "C" void kernel_launch(void* const* d_in, const int* in_sizes, int n_in,
                              void* d_out, int out_size) {
    const float* x    = (const float*)d_in[0];   // (4,2048,1024)
    const float* grid = (const float*)d_in[1];   // (1024,12)
    const float* coef = (const float*)d_in[2];   // (1024,2048,8)
    const float* sb   = (const float*)d_in[3];   // (1024,2048)
    const float* ssp  = (const float*)d_in[4];   // (1024,2048)
    float* out = (float*)d_out;                  // (4,2048,2048)

    prep_A_kernel<<<(NROWS * D_IN) / 256, 256>>>(x, grid);
    prep_W_kernel<<<(D_IN * D_OUT) / 256, 256>>>(coef, sb, ssp);

    cudaFuncSetAttribute(kan_gemm_kernel,
                         cudaFuncAttributeMaxDynamicSharedMemorySize, SMEM_TOTAL);
    kan_gemm_kernel<<<GRIDP, 512, SMEM_TOTAL>>>(out);
}

// round 6
// speedup vs baseline: 1.0275x; 1.0275x over previous
#include <cuda_runtime.h>
#include <cuda_fp16.h>
#include <cstdint>

// ============================================================================
// Problem constants
// ============================================================================
#define D_IN   1024
#define D_OUT  2048
#define NROWS  8192                 // 4 * 2048
// Logical K layout (2:4 sparse):
//   basis:  d*8 + l, l=0..7, permuted slots [0,4,1,5,2,6,3,7]  -> 8192
//   silu :  8192 + 4*dpair + {0..3} = [silu_2dp, 0, silu_2dp+1, 0] -> 2048
#define KLOG   10240
#define KSTORE 5120                 // stored (nonzero) K per row
#define KMETA  1280                 // metadata bytes per row (4b per 4-group)
#define BM     128
#define BN     256
#define BKL    64                   // logical k per step (stored 32)
#define NSTEPS (KLOG / BKL)         // 160
#define NSTAGES 4

// SMEM: A stored tiles (128 rows x 64B @ stride 80B), B (256 x 128B SW128),
// meta (128 rows x 8B)
#define SM_A_SZ   10240             // 128*80
#define SM_B_SZ   32768
#define SM_M_SZ   1024
#define SM_B_BASE (NSTAGES * SM_A_SZ)                    // 40960
#define SM_M_BASE (SM_B_BASE + NSTAGES * SM_B_SZ)        // 172032
#define SMEM_TOTAL (SM_M_BASE + NSTAGES * SM_M_SZ)       // 176128

// ============================================================================
// Device scratch (static __device__ arrays: sanctioned no-alloc workaround)
// ============================================================================
__device__ __half  g_A[(size_t)NROWS * KSTORE];   // 80 MB  stored A values
__device__ __half  g_W[(size_t)D_OUT * KLOG];     // 40 MB  dense-logical W
__device__ uint8_t g_meta[(size_t)NROWS * KMETA]; // 10 MB  2:4 metadata

// ============================================================================
// PTX helpers (base ISA only)
// ============================================================================
__device__ __forceinline__ uint32_t smem_u32(const void* p) {
    uint32_t a;
    asm("{ .reg .u64 t; cvta.to.shared.u64 t, %1; cvt.u32.u64 %0, t; }" : "=r"(a) : "l"(p));
    return a;
}
__device__ __forceinline__ void cp16(uint32_t dst, const void* src) {
    asm volatile("cp.async.cg.shared.global [%0], [%1], 16;" :: "r"(dst), "l"(src));
}
__device__ __forceinline__ void cp8(uint32_t dst, const void* src) {
    asm volatile("cp.async.ca.shared.global [%0], [%1], 8;" :: "r"(dst), "l"(src));
}
#define CP_COMMIT() asm volatile("cp.async.commit_group;" ::: "memory")
#define CP_WAIT_2() asm volatile("cp.async.wait_group 2;" ::: "memory")

__device__ __forceinline__ void ldsm_x4(uint32_t* r, uint32_t addr) {
    asm volatile("ldmatrix.sync.aligned.m8n8.x4.shared.b16 {%0,%1,%2,%3}, [%4];"
                 : "=r"(r[0]), "=r"(r[1]), "=r"(r[2]), "=r"(r[3]) : "r"(addr));
}
__device__ __forceinline__ uint32_t lds_u16(uint32_t addr) {
    uint32_t v;
    asm volatile("ld.shared.u16 %0, [%1];" : "=r"(v) : "r"(addr));
    return v;
}

// Sparse 2:4 mma: logical m16n8k32, A stored 16x16, f32 accumulate.
__device__ __forceinline__ void mma_sp(float* c, const uint32_t* a,
                                       uint32_t b0, uint32_t b1,
                                       uint32_t b2, uint32_t b3, uint32_t e) {
    asm volatile(
        "mma.sp::ordered_metadata.sync.aligned.m16n8k32.row.col.f32.f16.f16.f32 "
        "{%0,%1,%2,%3}, {%4,%5,%6,%7}, {%8,%9,%10,%11}, {%0,%1,%2,%3}, %12, 0x0;"
        : "+f"(c[0]), "+f"(c[1]), "+f"(c[2]), "+f"(c[3])
        : "r"(a[0]), "r"(a[1]), "r"(a[2]), "r"(a[3]),
          "r"(b0), "r"(b1), "r"(b2), "r"(b3), "r"(e));
}

// ============================================================================
// prep_A: Cox-de-Boor (proven-exact recursion) -> stored 2:4 values + metadata.
// Group0 = logical slots [s0,s4,s1,s5]; Group1 = [s2,s6,s3,s7].
//   i=0: g0=[B0,B1](0,2) g1=[B2,B3](0,2)
//   i=1: g0=[B4,B1](1,2) g1=[B2,B3](0,2)
//   i=2: g0=[B4,B5](1,3) g1=[B2,B3](0,2)
//   i=3: g0=[B4,B5](1,3) g1=[B6,B3](1,2)
//   i=4: g0=[B4,B5](1,3) g1=[B6,B7](1,3)
// nibble = idx0 | idx1<<2 -> 0x8 / 0x9 / 0xD
// ============================================================================
__global__ void prep_A_kernel(const float* __restrict__ x, const float* __restrict__ grid) {
    int idx = blockIdx.x * blockDim.x + threadIdx.x;   // n*1024 + d
    int d = idx & (D_IN - 1);
    int n = idx >> 10;
    float xv = x[idx];
    float gv[12];
#pragma unroll
    for (int m = 0; m < 12; m++) gv[m] = __ldg(grid + d * 12 + m);

    const float invh  = __frcp_rn(gv[1] - gv[0]);
    const float invp[3] = {invh, 0.5f * invh, (1.0f / 3.0f) * invh};

    float B[11];
#pragma unroll
    for (int m = 0; m < 11; m++)
        B[m] = (xv >= gv[m] && xv < gv[m + 1]) ? 1.0f : 0.0f;
#pragma unroll
    for (int p = 1; p <= 3; p++) {
        const float ip = invp[p - 1];
#pragma unroll
        for (int m = 0; m < 11 - p; m++) {
            float left  = (xv - gv[m]) * ip;
            float right = (gv[m + p + 1] - xv) * ip;
            B[m] = left * B[m] + right * B[m + 1];
        }
    }

    // interval index, exactly consistent with the indicator comparisons
    int i = (xv >= gv[4]) + (xv >= gv[5]) + (xv >= gv[6]) + (xv >= gv[7]);

    float p00, p01, p10, p11;
    uint32_t nib0, nib1;
    if (i == 0)      { p00 = B[0]; p01 = B[1]; nib0 = 0x8u; }
    else if (i == 1) { p00 = B[4]; p01 = B[1]; nib0 = 0x9u; }
    else             { p00 = B[4]; p01 = B[5]; nib0 = 0xDu; }
    if (i <= 2)      { p10 = B[2]; p11 = B[3]; nib1 = 0x8u; }
    else if (i == 3) { p10 = B[6]; p11 = B[3]; nib1 = 0x9u; }
    else             { p10 = B[6]; p11 = B[7]; nib1 = 0xDu; }

    __half2 h2[2];
    h2[0] = __floats2half2_rn(p00, p01);
    h2[1] = __floats2half2_rn(p10, p11);
    *reinterpret_cast<uint2*>(g_A + (size_t)n * KSTORE + d * 4) =
        *reinterpret_cast<uint2*>(h2);

    float s = xv * __frcp_rn(1.0f + __expf(-xv));
    g_A[(size_t)n * KSTORE + 4096 + d] = __float2half_rn(s);

    g_meta[(size_t)n * KMETA + d] = (uint8_t)(nib0 | (nib1 << 4));
    if (d < 256)    // silu region: [v,0,v,0] -> (0,2) both groups = 0x88
        g_meta[(size_t)n * KMETA + 1024 + d] = 0x88u;
}

// ============================================================================
// prep_W: dense-logical W with permuted basis slots + silu padding.
// ============================================================================
__global__ void prep_W_kernel(const float* __restrict__ coef,
                              const float* __restrict__ sb,
                              const float* __restrict__ ssp) {
    int idx = blockIdx.x * blockDim.x + threadIdx.x;  // d*2048 + o
    int o = idx & (D_OUT - 1);
    int d = idx >> 11;
    size_t doo = (size_t)d * D_OUT + o;
    float ss = ssp[doo];
    float c[8];
    float4 c0 = *reinterpret_cast<const float4*>(coef + doo * 8);
    float4 c1 = *reinterpret_cast<const float4*>(coef + doo * 8 + 4);
    c[0] = c0.x; c[1] = c0.y; c[2] = c0.z; c[3] = c0.w;
    c[4] = c1.x; c[5] = c1.y; c[6] = c1.z; c[7] = c1.w;
    const int perm[8] = {0, 4, 1, 5, 2, 6, 3, 7};
    __half2 h[4];
#pragma unroll
    for (int l = 0; l < 4; l++)
        h[l] = __floats2half2_rn(c[perm[2 * l]] * ss, c[perm[2 * l + 1]] * ss);
    *reinterpret_cast<uint4*>(g_W + (size_t)o * KLOG + d * 8) =
        *reinterpret_cast<uint4*>(h);
    // silu slot: logical 8192 + 4*(d/2) + 2*(d&1), pair [sb, 0]
    __half2 sv = __floats2half2_rn(sb[doo], 0.0f);
    *reinterpret_cast<__half2*>(g_W + (size_t)o * KLOG + 8192 + 4 * (d >> 1) + 2 * (d & 1)) = sv;
}

// ============================================================================
// Sparse GEMM: out[8192,2048] = A_sp @ W^T  (mma.sp m16n8k32, f32 acc)
// CTA 128x256, 8 warps (2x4), warp tile 64x64, BK_logical=64 (stored 32),
// 4-stage cp.async.  A stored rows @80B stride (bank-conflict-free ldsm).
// ============================================================================
__global__ __launch_bounds__(256, 1)
void kan_gemm_kernel(float* __restrict__ out) {
    extern __shared__ __align__(128) char smem[];
    const uint32_t sbase = smem_u32(smem);
    const int tid  = threadIdx.x;
    const int lane = tid & 31;
    const int wid  = tid >> 5;
    const int wm   = wid & 1;        // 2 m-bands of 64
    const int wn   = wid >> 1;       // 4 n-bands of 64
    const int n0 = blockIdx.x * BN;  // gridDim.x = 8 (fast: A band stays L2-hot)
    const int m0 = blockIdx.y * BM;

    // ---- fill thread mapping ----
    const int ar = tid >> 1;             // A stored row 0..127
    const int au = (tid & 1) * 2;        // A unit pair
    const int fr = tid >> 3;             // B base row 0..31
    const int fu = tid & 7;              // B unit
    const int fsw = (fu ^ (fr & 7)) << 4;

    auto fill = [&](int s, int k) {
        // A stored: 64B per row at stride 80
        const __half* Asrc = g_A + (size_t)(m0 + ar) * KSTORE + k * 32 + au * 8;
        uint32_t sA = sbase + s * SM_A_SZ + ar * 80 + au * 16;
        cp16(sA, Asrc);
        cp16(sA + 16, Asrc + 8);
        // B: 128B per row, SW128 swizzle
        const __half* Bsrc = g_W + (size_t)(n0 + fr) * KLOG + (size_t)k * BKL + fu * 8;
        uint32_t sB = sbase + SM_B_BASE + s * SM_B_SZ + fr * 128 + fsw;
#pragma unroll
        for (int i = 0; i < 8; i++)
            cp16(sB + i * 32 * 128, Bsrc + (size_t)i * 32 * KLOG);
        // meta: 8B per row
        if (tid < 128)
            cp8(sbase + SM_M_BASE + s * SM_M_SZ + tid * 8,
                g_meta + (size_t)(m0 + tid) * KMETA + k * 8);
    };

    fill(0, 0); CP_COMMIT();
    fill(1, 1); CP_COMMIT();
    fill(2, 2); CP_COMMIT();

    float acc[4][8][4];
#pragma unroll
    for (int a = 0; a < 4; a++)
#pragma unroll
        for (int j = 0; j < 8; j++)
#pragma unroll
            for (int cc = 0; cc < 4; cc++) acc[a][j][cc] = 0.0f;

    const int s7  = lane & 7;
    const int hi  = lane >> 4;
    const int r16 = lane & 15;
    const int g8  = lane >> 2;          // metadata row within 16
    const int kh  = lane & 1;           // metadata k-half (lanes %4 in {0,1} used)

    for (int k = 0; k < NSTEPS; k++) {
        const int s = k & (NSTAGES - 1);
        CP_WAIT_2();
        __syncthreads();
        if (k + 3 < NSTEPS) fill((k + 3) & (NSTAGES - 1), k + 3);
        CP_COMMIT();

        const uint32_t sA = sbase + s * SM_A_SZ;
        const uint32_t sB = sbase + SM_B_BASE + s * SM_B_SZ;
        const uint32_t sM = sbase + SM_M_BASE + s * SM_M_SZ;

#pragma unroll
        for (int c = 0; c < 2; c++) {           // two logical-k32 chunks
            // A stored frags (16x16 per a-tile)
            uint32_t af[4][4];
#pragma unroll
            for (int a = 0; a < 4; a++)
                ldsm_x4(af[a], sA + (uint32_t)(wm * 64 + a * 16 + r16) * 80
                               + c * 32 + hi * 16);
            // B frags: k16 chunks 2c, 2c+1
            uint32_t bf[4][2][4];
#pragma unroll
            for (int nb = 0; nb < 4; nb++)
#pragma unroll
                for (int h = 0; h < 2; h++) {
                    const int ch = 2 * c + h;
                    ldsm_x4(bf[nb][h],
                            sB + (uint32_t)(wn * 64 + nb * 16 + r16) * 128
                               + (((uint32_t)((ch * 2 + hi) ^ s7)) << 4));
                }
            // metadata regs per a-tile: rows g8 / g8+8, 16 bits each (k-half kh)
            uint32_t em[4];
#pragma unroll
            for (int a = 0; a < 4; a++) {
                const uint32_t rA = (uint32_t)(wm * 64 + a * 16 + g8);
                uint32_t lo  = lds_u16(sM + rA * 8 + c * 4 + kh * 2);
                uint32_t hi16 = lds_u16(sM + (rA + 8) * 8 + c * 4 + kh * 2);
                em[a] = lo | (hi16 << 16);
            }
#pragma unroll
            for (int a = 0; a < 4; a++)
#pragma unroll
                for (int nb = 0; nb < 4; nb++) {
                    mma_sp(acc[a][nb * 2 + 0], af[a],
                           bf[nb][0][0], bf[nb][0][2], bf[nb][1][0], bf[nb][1][2], em[a]);
                    mma_sp(acc[a][nb * 2 + 1], af[a],
                           bf[nb][0][1], bf[nb][0][3], bf[nb][1][1], bf[nb][1][3], em[a]);
                }
        }
    }

    // ---- epilogue ----
    const int g = lane >> 2;
    const int t = lane & 3;
    const int orow0 = m0 + wm * 64 + g;
    const int ocol0 = n0 + wn * 64 + t * 2;
#pragma unroll
    for (int a = 0; a < 4; a++) {
        float* p0 = out + (size_t)(orow0 + a * 16) * D_OUT + ocol0;
        float* p1 = p0 + 8 * D_OUT;
#pragma unroll
        for (int j = 0; j < 8; j++) {
            *reinterpret_cast<float2*>(p0 + j * 8) = make_float2(acc[a][j][0], acc[a][j][1]);
            *reinterpret_cast<float2*>(p1 + j * 8) = make_float2(acc[a][j][2], acc[a][j][3]);
        }
    }
}

// ============================================================================
// Host launch (graph-capturable: kernel launches only)
// ============================================================================
extern "C" void kernel_launch(void* const* d_in, const int* in_sizes, int n_in,
                              void* d_out, int out_size) {
    const float* x    = (const float*)d_in[0];   // (4,2048,1024)
    const float* grid = (const float*)d_in[1];   // (1024,12)
    const float* coef = (const float*)d_in[2];   // (1024,2048,8)
    const float* sb   = (const float*)d_in[3];   // (1024,2048)
    const float* ssp  = (const float*)d_in[4];   // (1024,2048)
    float* out = (float*)d_out;                  // (4,2048,2048)

    prep_A_kernel<<<(NROWS * D_IN) / 256, 256>>>(x, grid);
    prep_W_kernel<<<(D_IN * D_OUT) / 256, 256>>>(coef, sb, ssp);

    cudaFuncSetAttribute(kan_gemm_kernel,
                         cudaFuncAttributeMaxDynamicSharedMemorySize, SMEM_TOTAL);
    kan_gemm_kernel<<<dim3(D_OUT / BN, NROWS / BM), 256, SMEM_TOTAL>>>(out);
}